// round 5
// baseline (speedup 1.0000x reference)
#include <cuda_runtime.h>
#include <cuda_bf16.h>
#include <math.h>

#define FULL_MASK 0xffffffffu

#define BATCH   32
#define DIM     4096
#define NQ      32
#define NKV     8
#define HD      128
#define QKV_N   6144
#define REP     4
#define KSPLIT  16
#define KLEN    (DIM / KSPLIT)   // 256
#define TSPLIT  16
#define CHUNK_MAX 128            // ceil(2048 / TSPLIT)

// Scratch (device globals; no allocation allowed)
__device__ float g_qkv[BATCH * QKV_N];                    // post-reduce, post-RoPE
__device__ float g_att[BATCH * DIM];                      // attention output, pre-wo
__device__ float g_part_qkv[KSPLIT][BATCH][QKV_N];        // split-K partials
__device__ float g_part_o[KSPLIT][BATCH][DIM];
__device__ float g_attp[TSPLIT][BATCH][NKV][REP][HD];     // split-T partial A*V (unnormalized)
__device__ float g_attm[TSPLIT][BATCH][NKV][REP];         // split-T local max
__device__ float g_atts[TSPLIT][BATCH][NKV][REP];         // split-T local expsum

// ---------------- packed fp32x2 helpers (Blackwell) ----------------
__device__ __forceinline__ unsigned long long pack2(float lo, float hi) {
    unsigned long long r;
    asm("mov.b64 %0, {%1, %2};" : "=l"(r) : "f"(lo), "f"(hi));
    return r;
}
__device__ __forceinline__ void fma2(unsigned long long& d, unsigned long long a, unsigned long long b) {
    asm("fma.rn.f32x2 %0, %1, %2, %0;" : "+l"(d) : "l"(a), "l"(b));
}
__device__ __forceinline__ float2 unpack2(unsigned long long v) {
    float lo, hi;
    asm("mov.b64 {%0, %1}, %2;" : "=f"(lo), "=f"(hi) : "l"(v));
    return make_float2(lo, hi);
}

// ---------------- Split-K skinny GEMM tile ----------------
// M = 32 rows, N-tile = 128 cols, 128 threads, 4 cols per thread.
// Cpart[m, ccol0+c+32q] = sum_{k in [kbeg, kbeg+KLEN)} A[m,k] * W[wrow0+c+32q, k]
__device__ __forceinline__ void gemm_tile(const float* __restrict__ A,
                                          const float* __restrict__ W,
                                          float* __restrict__ C,
                                          int K, int ldc, int wrow0, int ccol0,
                                          int kbeg)
{
    __shared__ __align__(16) float As[32][36];    // [kk][m], pad 36 -> 16B-aligned row pairs
    __shared__ float Ws[32][132];                 // [kk][n]

    const int tid   = threadIdx.x;
    const int c     = tid & 31;
    const int rbase = (tid >> 5) << 3;            // 0,8,16,24

    unsigned long long acc[4][4];
#pragma unroll
    for (int p = 0; p < 4; p++)
#pragma unroll
        for (int q = 0; q < 4; q++) acc[p][q] = 0ull;

    for (int k0 = kbeg; k0 < kbeg + KLEN; k0 += 32) {
        // A tile: 32 rows x 32 k
#pragma unroll
        for (int j = 0; j < 8; j++) {
            int e = tid + j * 128;
            int kk = e & 31, m = e >> 5;
            As[kk][m] = A[(size_t)m * K + k0 + kk];
        }
        // W tile: 128 cols x 32 k
#pragma unroll
        for (int j = 0; j < 32; j++) {
            int e = tid + j * 128;
            int kk = e & 31, n = e >> 5;
            Ws[kk][n] = W[(size_t)(wrow0 + n) * K + k0 + kk];
        }
        __syncthreads();

#pragma unroll
        for (int kk = 0; kk < 32; kk++) {
            const ulonglong2* ap = reinterpret_cast<const ulonglong2*>(&As[kk][rbase]);
            ulonglong2 u0 = ap[0];
            ulonglong2 u1 = ap[1];
            float w0 = Ws[kk][c];
            float w1 = Ws[kk][c + 32];
            float w2 = Ws[kk][c + 64];
            float w3 = Ws[kk][c + 96];
            unsigned long long W0 = pack2(w0, w0);
            unsigned long long W1 = pack2(w1, w1);
            unsigned long long W2 = pack2(w2, w2);
            unsigned long long W3 = pack2(w3, w3);
            fma2(acc[0][0], u0.x, W0); fma2(acc[1][0], u0.y, W0);
            fma2(acc[2][0], u1.x, W0); fma2(acc[3][0], u1.y, W0);
            fma2(acc[0][1], u0.x, W1); fma2(acc[1][1], u0.y, W1);
            fma2(acc[2][1], u1.x, W1); fma2(acc[3][1], u1.y, W1);
            fma2(acc[0][2], u0.x, W2); fma2(acc[1][2], u0.y, W2);
            fma2(acc[2][2], u1.x, W2); fma2(acc[3][2], u1.y, W2);
            fma2(acc[0][3], u0.x, W3); fma2(acc[1][3], u0.y, W3);
            fma2(acc[2][3], u1.x, W3); fma2(acc[3][3], u1.y, W3);
        }
        __syncthreads();
    }

#pragma unroll
    for (int p = 0; p < 4; p++) {
#pragma unroll
        for (int q = 0; q < 4; q++) {
            float2 v = unpack2(acc[p][q]);
            int m   = rbase + 2 * p;
            int col = ccol0 + c + 32 * q;
            C[(size_t)m * ldc + col]       = v.x;
            C[(size_t)(m + 1) * ldc + col] = v.y;
        }
    }
}

// ---------------- QKV projection: grid (48, KSPLIT) ----------------
__global__ void gemm_qkv_kernel(const float* __restrict__ x,
                                const float* __restrict__ wq,
                                const float* __restrict__ wk,
                                const float* __restrict__ wv)
{
    int n0 = blockIdx.x * 128;
    int kbeg = blockIdx.y * KLEN;
    const float* W;
    int wrow0;
    if (n0 < 4096)      { W = wq; wrow0 = n0; }
    else if (n0 < 5120) { W = wk; wrow0 = n0 - 4096; }
    else                { W = wv; wrow0 = n0 - 5120; }
    gemm_tile(x, W, &g_part_qkv[blockIdx.y][0][0], DIM, QKV_N, wrow0, n0, kbeg);
}

// ---------------- Output projection: grid (32, KSPLIT) ----------------
__global__ void gemm_o_kernel(const float* __restrict__ wo)
{
    int n0 = blockIdx.x * 128;
    int kbeg = blockIdx.y * KLEN;
    gemm_tile(g_att, wo, &g_part_o[blockIdx.y][0][0], DIM, DIM, n0, n0, kbeg);
}

// ---------------- QKV reduce + fused RoPE ----------------
__global__ void reduce_qkv_rope(const float* __restrict__ cosv,
                                const float* __restrict__ sinv)
{
    int idx = blockIdx.x * 256 + threadIdx.x;       // pair index
    if (idx >= BATCH * (QKV_N / 2)) return;
    int b  = idx / (QKV_N / 2);
    int pr = idx - b * (QKV_N / 2);
    int col = pr * 2;

    float sx = 0.f, sy = 0.f;
#pragma unroll
    for (int ks = 0; ks < KSPLIT; ks++) {
        float2 v = *reinterpret_cast<const float2*>(&g_part_qkv[ks][b][col]);
        sx += v.x; sy += v.y;
    }
    float2 o;
    if (col < 5120) {   // q + k get RoPE
        int d2 = (col & (HD - 1)) >> 1;
        float c = cosv[d2], s = sinv[d2];
        o.x = sx * c - sy * s;
        o.y = sx * s + sy * c;
    } else {
        o.x = sx; o.y = sy;
    }
    *reinterpret_cast<float2*>(&g_qkv[(size_t)b * QKV_N + col]) = o;
}

// ---------------- Output reduce -> d_out ----------------
__global__ void reduce_o(float* __restrict__ out)
{
    int idx = blockIdx.x * 256 + threadIdx.x;       // pair index
    if (idx >= BATCH * (DIM / 2)) return;
    int b  = idx / (DIM / 2);
    int pr = idx - b * (DIM / 2);
    int col = pr * 2;
    float sx = 0.f, sy = 0.f;
#pragma unroll
    for (int ks = 0; ks < KSPLIT; ks++) {
        float2 v = *reinterpret_cast<const float2*>(&g_part_o[ks][b][col]);
        sx += v.x; sy += v.y;
    }
    *reinterpret_cast<float2*>(&out[(size_t)b * DIM + col]) = make_float2(sx, sy);
}

// ---------------- Attention partials: grid (NKV, BATCH, TSPLIT), 512 thr ----------------
__global__ void attn_part_kernel(const float* __restrict__ cache_k,
                                 const float* __restrict__ cache_v,
                                 const int* __restrict__ sp_ptr,
                                 int max_seq)
{
    const int g    = blockIdx.x;
    const int b    = blockIdx.y;
    const int ts   = blockIdx.z;
    const int tid  = threadIdx.x;     // 0..511
    const int lane = tid & 31;
    const int w    = tid >> 5;        // 0..15
    const int d    = tid & (HD - 1);
    const int r    = tid >> 7;        // 0..3
    const int sp   = *sp_ptr;
    const int T    = sp + 1;
    const int chunk = (T + TSPLIT - 1) / TSPLIT;
    const int t0   = ts * chunk;
    const int t1   = min(t0 + chunk, T);

    if (t0 >= T) {     // empty split
        if (tid < REP) { g_attm[ts][b][g][tid] = -3.0e38f; g_atts[ts][b][g][tid] = 0.f; }
        g_attp[ts][b][g][r][d] = 0.f;
        return;
    }
    const int n = t1 - t0;            // <= CHUNK_MAX

    __shared__ float sc[REP][CHUNK_MAX];
    __shared__ float q4s[REP][HD];
    __shared__ float red[16];
    __shared__ float rmax[REP];
    __shared__ float rsum[REP];

    for (int i = tid; i < REP * HD; i += 512) {
        int rr = i >> 7, dd = i & (HD - 1);
        q4s[rr][dd] = g_qkv[(size_t)b * QKV_N + (g * REP + rr) * HD + dd];
    }
    __syncthreads();

    float4 q0 = reinterpret_cast<const float4*>(q4s[0])[lane];
    float4 q1 = reinterpret_cast<const float4*>(q4s[1])[lane];
    float4 q2 = reinterpret_cast<const float4*>(q4s[2])[lane];
    float4 q3 = reinterpret_cast<const float4*>(q4s[3])[lane];

    const float* knew = &g_qkv[(size_t)b * QKV_N + 4096 + g * HD];
    const float* vnew = &g_qkv[(size_t)b * QKV_N + 5120 + g * HD];
    const float scale = 0.08838834764831845f;   // 1/sqrt(128)

    // ---- scores: warp-per-t across 16 warps ----
    for (int t = t0 + w; t < t1; t += 16) {
        const float* kp = (t < sp)
            ? &cache_k[(((size_t)b * max_seq + t) * NKV + g) * HD]
            : knew;
        float4 kv = reinterpret_cast<const float4*>(kp)[lane];
        float p0 = q0.x * kv.x + q0.y * kv.y + q0.z * kv.z + q0.w * kv.w;
        float p1 = q1.x * kv.x + q1.y * kv.y + q1.z * kv.z + q1.w * kv.w;
        float p2 = q2.x * kv.x + q2.y * kv.y + q2.z * kv.z + q2.w * kv.w;
        float p3 = q3.x * kv.x + q3.y * kv.y + q3.z * kv.z + q3.w * kv.w;
#pragma unroll
        for (int off = 16; off; off >>= 1) {
            p0 += __shfl_xor_sync(FULL_MASK, p0, off);
            p1 += __shfl_xor_sync(FULL_MASK, p1, off);
            p2 += __shfl_xor_sync(FULL_MASK, p2, off);
            p3 += __shfl_xor_sync(FULL_MASK, p3, off);
        }
        if (lane == 0) {
            sc[0][t - t0] = p0 * scale; sc[1][t - t0] = p1 * scale;
            sc[2][t - t0] = p2 * scale; sc[3][t - t0] = p3 * scale;
        }
    }
    __syncthreads();

    // ---- local softmax (max, exp, sum) per rep ----
    for (int rr = 0; rr < REP; rr++) {
        float m = -3.0e38f;
        for (int t = tid; t < n; t += 512) m = fmaxf(m, sc[rr][t]);
#pragma unroll
        for (int off = 16; off; off >>= 1) m = fmaxf(m, __shfl_xor_sync(FULL_MASK, m, off));
        if (lane == 0) red[w] = m;
        __syncthreads();
        if (tid == 0) {
            float mm = red[0];
            for (int i = 1; i < 16; i++) mm = fmaxf(mm, red[i]);
            rmax[rr] = mm;
        }
        __syncthreads();
        m = rmax[rr];

        float s = 0.f;
        for (int t = tid; t < n; t += 512) {
            float e = __expf(sc[rr][t] - m);
            sc[rr][t] = e;
            s += e;
        }
#pragma unroll
        for (int off = 16; off; off >>= 1) s += __shfl_xor_sync(FULL_MASK, s, off);
        if (lane == 0) red[w] = s;
        __syncthreads();
        if (tid == 0) {
            float ss = 0.f;
            for (int i = 0; i < 16; i++) ss += red[i];
            rsum[rr] = ss;
        }
        __syncthreads();
    }

    // ---- partial A @ V: thread (r, d) ----
    float a = 0.f;
#pragma unroll 8
    for (int t = t0; t < t1; t++) {
        float v = (t < sp)
            ? cache_v[(((size_t)b * max_seq + t) * NKV + g) * HD + d]
            : vnew[d];
        a += sc[r][t - t0] * v;
    }
    g_attp[ts][b][g][r][d] = a;
    if (tid < REP) {
        g_attm[ts][b][g][tid] = rmax[tid];
        g_atts[ts][b][g][tid] = rsum[tid];
    }
}

// ---------------- Attention combine: grid (NKV, BATCH), 512 thr ----------------
__global__ void attn_combine_kernel()
{
    const int g   = blockIdx.x;
    const int b   = blockIdx.y;
    const int tid = threadIdx.x;
    const int d   = tid & (HD - 1);
    const int r   = tid >> 7;

    float M = -3.0e38f;
#pragma unroll
    for (int ts = 0; ts < TSPLIT; ts++) M = fmaxf(M, g_attm[ts][b][g][r]);

    float S = 0.f, a = 0.f;
#pragma unroll
    for (int ts = 0; ts < TSPLIT; ts++) {
        float f = __expf(g_attm[ts][b][g][r] - M);
        S += g_atts[ts][b][g][r] * f;
        a += g_attp[ts][b][g][r][d] * f;
    }
    g_att[(size_t)b * DIM + (g * REP + r) * HD + d] = a / S;
}

// ---------------- launch ----------------
extern "C" void kernel_launch(void* const* d_in, const int* in_sizes, int n_in,
                              void* d_out, int out_size)
{
    const float* x  = (const float*)d_in[0];
    const float* wq = (const float*)d_in[1];
    const float* wk = (const float*)d_in[2];
    const float* wv = (const float*)d_in[3];
    const float* wo = (const float*)d_in[4];
    const float* fc = (const float*)d_in[5];
    const float* fs = (const float*)d_in[6];
    const float* ck = (const float*)d_in[7];
    const float* cv = (const float*)d_in[8];
    const int*   sp = (const int*)d_in[9];

    int max_seq = in_sizes[7] / (BATCH * NKV * HD);

    gemm_qkv_kernel<<<dim3(QKV_N / 128, KSPLIT), 128>>>(x, wq, wk, wv);
    reduce_qkv_rope<<<(BATCH * (QKV_N / 2) + 255) / 256, 256>>>(fc, fs);
    attn_part_kernel<<<dim3(NKV, BATCH, TSPLIT), 512>>>(ck, cv, sp, max_seq);
    attn_combine_kernel<<<dim3(NKV, BATCH), 512>>>();
    gemm_o_kernel<<<dim3(DIM / 128, KSPLIT), 128>>>(wo);
    reduce_o<<<(BATCH * (DIM / 2) + 255) / 256, 256>>>((float*)d_out);
}

// round 6
// speedup vs baseline: 1.1241x; 1.1241x over previous
#include <cuda_runtime.h>
#include <cuda_bf16.h>
#include <math.h>

#define FULL_MASK 0xffffffffu

#define BATCH   32
#define DIM     4096
#define NQ      32
#define NKV     8
#define HD      128
#define QKV_N   6144
#define REP     4
#define KSPLIT  16
#define KLEN    (DIM / KSPLIT)   // 256
#define TSPLIT  16
#define CHUNK_MAX 128            // ceil(2048 / TSPLIT)

// Scratch (device globals; no allocation allowed)
__device__ float g_qkv[BATCH * QKV_N];                    // post-reduce, post-RoPE
__device__ float g_att[BATCH * DIM];                      // attention output, pre-wo
__device__ float g_part_qkv[KSPLIT][BATCH][QKV_N];        // split-K partials
__device__ float g_part_o[KSPLIT][BATCH][DIM];
__device__ float g_attp[TSPLIT][BATCH][NKV][REP][HD];     // split-T partial A*V (unnormalized)
__device__ float g_attm[TSPLIT][BATCH][NKV][REP];         // split-T local max
__device__ float g_atts[TSPLIT][BATCH][NKV][REP];         // split-T local expsum

// ---------------- packed fp32x2 helpers (Blackwell) ----------------
__device__ __forceinline__ unsigned long long pack2(float lo, float hi) {
    unsigned long long r;
    asm("mov.b64 %0, {%1, %2};" : "=l"(r) : "f"(lo), "f"(hi));
    return r;
}
__device__ __forceinline__ void fma2(unsigned long long& d, unsigned long long a, unsigned long long b) {
    asm("fma.rn.f32x2 %0, %1, %2, %0;" : "+l"(d) : "l"(a), "l"(b));
}
__device__ __forceinline__ float2 unpack2(unsigned long long v) {
    float lo, hi;
    asm("mov.b64 {%0, %1}, %2;" : "=f"(lo), "=f"(hi) : "l"(v));
    return make_float2(lo, hi);
}

// ---------------- Split-K skinny GEMM tile (round-4 proven shape) ----------------
// M = 32 rows, N-tile = 64 cols, 128 threads, 2 cols per thread.
// Cpart[m, ccol0+c(+32)] = sum_{k in [kbeg, kbeg+KLEN)} A[m,k] * W[wrow0+c(+32), k]
__device__ __forceinline__ void gemm_tile(const float* __restrict__ A,
                                          const float* __restrict__ W,
                                          float* __restrict__ C,
                                          int K, int ldc, int wrow0, int ccol0,
                                          int kbeg)
{
    __shared__ __align__(16) float As[32][34];   // [kk][m]
    __shared__ float Ws[32][65];                 // [kk][n]

    const int tid   = threadIdx.x;
    const int c     = tid & 31;
    const int rbase = (tid >> 5) << 3;           // 0,8,16,24

    unsigned long long acc[4][2];
#pragma unroll
    for (int p = 0; p < 4; p++) { acc[p][0] = 0ull; acc[p][1] = 0ull; }

    for (int k0 = kbeg; k0 < kbeg + KLEN; k0 += 32) {
        // A tile: 32 rows x 32 k = 256 float4; 2 per thread
#pragma unroll
        for (int j = 0; j < 2; j++) {
            int e  = tid + j * 128;              // float4 index
            int m  = e >> 3;
            int kk = (e & 7) * 4;
            float4 v = *reinterpret_cast<const float4*>(&A[(size_t)m * K + k0 + kk]);
            As[kk + 0][m] = v.x; As[kk + 1][m] = v.y;
            As[kk + 2][m] = v.z; As[kk + 3][m] = v.w;
        }
        // W tile: 64 cols x 32 k = 512 float4; 4 per thread
#pragma unroll
        for (int j = 0; j < 4; j++) {
            int e  = tid + j * 128;
            int n  = e >> 3;
            int kk = (e & 7) * 4;
            float4 v = *reinterpret_cast<const float4*>(&W[(size_t)(wrow0 + n) * K + k0 + kk]);
            Ws[kk + 0][n] = v.x; Ws[kk + 1][n] = v.y;
            Ws[kk + 2][n] = v.z; Ws[kk + 3][n] = v.w;
        }
        __syncthreads();

#pragma unroll
        for (int kk = 0; kk < 32; kk++) {
            const unsigned long long* ap =
                reinterpret_cast<const unsigned long long*>(&As[kk][rbase]);
            unsigned long long a0 = ap[0], a1 = ap[1], a2 = ap[2], a3 = ap[3];
            float w0 = Ws[kk][c];
            float w1 = Ws[kk][c + 32];
            unsigned long long W0 = pack2(w0, w0);
            unsigned long long W1 = pack2(w1, w1);
            fma2(acc[0][0], a0, W0); fma2(acc[1][0], a1, W0);
            fma2(acc[2][0], a2, W0); fma2(acc[3][0], a3, W0);
            fma2(acc[0][1], a0, W1); fma2(acc[1][1], a1, W1);
            fma2(acc[2][1], a2, W1); fma2(acc[3][1], a3, W1);
        }
        __syncthreads();
    }

#pragma unroll
    for (int p = 0; p < 4; p++) {
#pragma unroll
        for (int cc = 0; cc < 2; cc++) {
            float2 v = unpack2(acc[p][cc]);
            int m   = rbase + 2 * p;
            int col = ccol0 + c + 32 * cc;
            C[(size_t)m * ldc + col]       = v.x;
            C[(size_t)(m + 1) * ldc + col] = v.y;
        }
    }
}

// ---------------- QKV projection: grid (96, KSPLIT) ----------------
__global__ void gemm_qkv_kernel(const float* __restrict__ x,
                                const float* __restrict__ wq,
                                const float* __restrict__ wk,
                                const float* __restrict__ wv)
{
    int n0 = blockIdx.x * 64;
    int kbeg = blockIdx.y * KLEN;
    const float* W;
    int wrow0;
    if (n0 < 4096)      { W = wq; wrow0 = n0; }
    else if (n0 < 5120) { W = wk; wrow0 = n0 - 4096; }
    else                { W = wv; wrow0 = n0 - 5120; }
    gemm_tile(x, W, &g_part_qkv[blockIdx.y][0][0], DIM, QKV_N, wrow0, n0, kbeg);
}

// ---------------- Output projection: grid (64, KSPLIT) ----------------
__global__ void gemm_o_kernel(const float* __restrict__ wo)
{
    int n0 = blockIdx.x * 64;
    int kbeg = blockIdx.y * KLEN;
    gemm_tile(g_att, wo, &g_part_o[blockIdx.y][0][0], DIM, DIM, n0, n0, kbeg);
}

// ---------------- QKV reduce + fused RoPE ----------------
__global__ void reduce_qkv_rope(const float* __restrict__ cosv,
                                const float* __restrict__ sinv)
{
    int idx = blockIdx.x * 256 + threadIdx.x;       // pair index
    if (idx >= BATCH * (QKV_N / 2)) return;
    int b  = idx / (QKV_N / 2);
    int pr = idx - b * (QKV_N / 2);
    int col = pr * 2;

    float sx = 0.f, sy = 0.f;
#pragma unroll
    for (int ks = 0; ks < KSPLIT; ks++) {
        float2 v = *reinterpret_cast<const float2*>(&g_part_qkv[ks][b][col]);
        sx += v.x; sy += v.y;
    }
    float2 o;
    if (col < 5120) {   // q + k get RoPE
        int d2 = (col & (HD - 1)) >> 1;
        float c = cosv[d2], s = sinv[d2];
        o.x = sx * c - sy * s;
        o.y = sx * s + sy * c;
    } else {
        o.x = sx; o.y = sy;
    }
    *reinterpret_cast<float2*>(&g_qkv[(size_t)b * QKV_N + col]) = o;
}

// ---------------- Output reduce -> d_out ----------------
__global__ void reduce_o(float* __restrict__ out)
{
    int idx = blockIdx.x * 256 + threadIdx.x;       // pair index
    if (idx >= BATCH * (DIM / 2)) return;
    int b  = idx / (DIM / 2);
    int pr = idx - b * (DIM / 2);
    int col = pr * 2;
    float sx = 0.f, sy = 0.f;
#pragma unroll
    for (int ks = 0; ks < KSPLIT; ks++) {
        float2 v = *reinterpret_cast<const float2*>(&g_part_o[ks][b][col]);
        sx += v.x; sy += v.y;
    }
    *reinterpret_cast<float2*>(&out[(size_t)b * DIM + col]) = make_float2(sx, sy);
}

// ---------------- Attention partials: grid (NKV, BATCH, TSPLIT), 512 thr ----------------
__global__ void attn_part_kernel(const float* __restrict__ cache_k,
                                 const float* __restrict__ cache_v,
                                 const int* __restrict__ sp_ptr,
                                 int max_seq)
{
    const int g    = blockIdx.x;
    const int b    = blockIdx.y;
    const int ts   = blockIdx.z;
    const int tid  = threadIdx.x;     // 0..511
    const int lane = tid & 31;
    const int w    = tid >> 5;        // 0..15
    const int d    = tid & (HD - 1);
    const int r    = tid >> 7;        // 0..3
    const int sp   = *sp_ptr;
    const int T    = sp + 1;
    const int chunk = (T + TSPLIT - 1) / TSPLIT;
    const int t0   = ts * chunk;
    const int t1   = min(t0 + chunk, T);

    if (t0 >= T) {     // empty split
        if (tid < REP) { g_attm[ts][b][g][tid] = -3.0e38f; g_atts[ts][b][g][tid] = 0.f; }
        g_attp[ts][b][g][r][d] = 0.f;
        return;
    }
    const int n = t1 - t0;            // <= CHUNK_MAX

    __shared__ float sc[REP][CHUNK_MAX];
    __shared__ float q4s[REP][HD];
    __shared__ float redm[REP][4];
    __shared__ float reds[REP][4];
    __shared__ float rmax[REP];
    __shared__ float rsum[REP];

    for (int i = tid; i < REP * HD; i += 512) {
        int rr = i >> 7, dd = i & (HD - 1);
        q4s[rr][dd] = g_qkv[(size_t)b * QKV_N + (g * REP + rr) * HD + dd];
    }
    __syncthreads();

    float4 q0 = reinterpret_cast<const float4*>(q4s[0])[lane];
    float4 q1 = reinterpret_cast<const float4*>(q4s[1])[lane];
    float4 q2 = reinterpret_cast<const float4*>(q4s[2])[lane];
    float4 q3 = reinterpret_cast<const float4*>(q4s[3])[lane];

    const float* knew = &g_qkv[(size_t)b * QKV_N + 4096 + g * HD];
    const float* vnew = &g_qkv[(size_t)b * QKV_N + 5120 + g * HD];
    const float scale = 0.08838834764831845f;   // 1/sqrt(128)

    // ---- scores: warp-per-t across 16 warps ----
    for (int t = t0 + w; t < t1; t += 16) {
        const float* kp = (t < sp)
            ? &cache_k[(((size_t)b * max_seq + t) * NKV + g) * HD]
            : knew;
        float4 kv = reinterpret_cast<const float4*>(kp)[lane];
        float p0 = q0.x * kv.x + q0.y * kv.y + q0.z * kv.z + q0.w * kv.w;
        float p1 = q1.x * kv.x + q1.y * kv.y + q1.z * kv.z + q1.w * kv.w;
        float p2 = q2.x * kv.x + q2.y * kv.y + q2.z * kv.z + q2.w * kv.w;
        float p3 = q3.x * kv.x + q3.y * kv.y + q3.z * kv.z + q3.w * kv.w;
#pragma unroll
        for (int off = 16; off; off >>= 1) {
            p0 += __shfl_xor_sync(FULL_MASK, p0, off);
            p1 += __shfl_xor_sync(FULL_MASK, p1, off);
            p2 += __shfl_xor_sync(FULL_MASK, p2, off);
            p3 += __shfl_xor_sync(FULL_MASK, p3, off);
        }
        if (lane == 0) {
            sc[0][t - t0] = p0 * scale; sc[1][t - t0] = p1 * scale;
            sc[2][t - t0] = p2 * scale; sc[3][t - t0] = p3 * scale;
        }
    }
    __syncthreads();

    // ---- local softmax: all 4 reps in parallel (128 threads per rep) ----
    {
        const int rr = r;             // tid>>7
        const int tt = tid & 127;
        const int wq4 = (tid >> 5) & 3;  // warp within rep group

        float mv = (tt < n) ? sc[rr][tt] : -3.0e38f;
#pragma unroll
        for (int off = 16; off; off >>= 1) mv = fmaxf(mv, __shfl_xor_sync(FULL_MASK, mv, off));
        if (lane == 0) redm[rr][wq4] = mv;
        __syncthreads();
        float m = fmaxf(fmaxf(redm[rr][0], redm[rr][1]),
                        fmaxf(redm[rr][2], redm[rr][3]));

        float e = 0.f;
        if (tt < n) {
            e = __expf(sc[rr][tt] - m);
            sc[rr][tt] = e;
        }
        float s = e;
#pragma unroll
        for (int off = 16; off; off >>= 1) s += __shfl_xor_sync(FULL_MASK, s, off);
        if (lane == 0) reds[rr][wq4] = s;
        __syncthreads();
        if (tt == 0) {
            rmax[rr] = m;
            rsum[rr] = reds[rr][0] + reds[rr][1] + reds[rr][2] + reds[rr][3];
        }
    }
    __syncthreads();

    // ---- partial A @ V: thread (r, d) ----
    float a = 0.f;
#pragma unroll 8
    for (int t = t0; t < t1; t++) {
        float v = (t < sp)
            ? cache_v[(((size_t)b * max_seq + t) * NKV + g) * HD + d]
            : vnew[d];
        a += sc[r][t - t0] * v;
    }
    g_attp[ts][b][g][r][d] = a;
    if (tid < REP) {
        g_attm[ts][b][g][tid] = rmax[tid];
        g_atts[ts][b][g][tid] = rsum[tid];
    }
}

// ---------------- Attention combine: grid (NKV, BATCH), 512 thr ----------------
__global__ void attn_combine_kernel()
{
    const int g   = blockIdx.x;
    const int b   = blockIdx.y;
    const int tid = threadIdx.x;
    const int d   = tid & (HD - 1);
    const int r   = tid >> 7;

    float M = -3.0e38f;
#pragma unroll
    for (int ts = 0; ts < TSPLIT; ts++) M = fmaxf(M, g_attm[ts][b][g][r]);

    float S = 0.f, a = 0.f;
#pragma unroll
    for (int ts = 0; ts < TSPLIT; ts++) {
        float f = __expf(g_attm[ts][b][g][r] - M);
        S += g_atts[ts][b][g][r] * f;
        a += g_attp[ts][b][g][r][d] * f;
    }
    g_att[(size_t)b * DIM + (g * REP + r) * HD + d] = a / S;
}

// ---------------- launch ----------------
extern "C" void kernel_launch(void* const* d_in, const int* in_sizes, int n_in,
                              void* d_out, int out_size)
{
    const float* x  = (const float*)d_in[0];
    const float* wq = (const float*)d_in[1];
    const float* wk = (const float*)d_in[2];
    const float* wv = (const float*)d_in[3];
    const float* wo = (const float*)d_in[4];
    const float* fc = (const float*)d_in[5];
    const float* fs = (const float*)d_in[6];
    const float* ck = (const float*)d_in[7];
    const float* cv = (const float*)d_in[8];
    const int*   sp = (const int*)d_in[9];

    int max_seq = in_sizes[7] / (BATCH * NKV * HD);

    gemm_qkv_kernel<<<dim3(QKV_N / 64, KSPLIT), 128>>>(x, wq, wk, wv);
    reduce_qkv_rope<<<(BATCH * (QKV_N / 2) + 255) / 256, 256>>>(fc, fs);
    attn_part_kernel<<<dim3(NKV, BATCH, TSPLIT), 512>>>(ck, cv, sp, max_seq);
    attn_combine_kernel<<<dim3(NKV, BATCH), 512>>>();
    gemm_o_kernel<<<dim3(DIM / 64, KSPLIT), 128>>>(wo);
    reduce_o<<<(BATCH * (DIM / 2) + 255) / 256, 256>>>((float*)d_out);
}